// round 7
// baseline (speedup 1.0000x reference)
#include <cuda_runtime.h>
#include <math.h>

#define BB    8
#define CC    256
#define NCLS  20
#define APER  2
#define LTOT  3584
#define ATOT  7168
#define KTOP  1000
#define NSORT 8192

// ---------------- scratch (device globals; no allocation) ----------------
__device__ float g_bufA[BB * CC * LTOT];
__device__ float g_bufB[BB * CC * LTOT];
__device__ float g_logits[BB * APER * NCLS * LTOT];
__device__ float g_regs[BB * APER * 2 * LTOT];
__device__ float g_segs[BB * ATOT * 2];
__device__ unsigned long long g_keys[BB * NSORT];
__device__ unsigned long long g_topkeys[BB * KTOP];

// ---------------- 256->256 k=3 pad=1 conv (+ReLU), Eigen-blocked ---------
// out = ((S_kw0 + S_kw1) + S_kw2) + bias ; each S = sequential fma chain
// over ci = 0..255 (Eigen gemm kc=256 blocking; ci-fastest patch layout).
// Block: 128 co x 128 l, 512 threads, per-thread 4co x 8l tile,
// part[] = current kw partial, carry[] = combined prior blocks.
template <bool RELU>
__global__ void __launch_bounds__(512, 1) conv256_kernel(
    const float* __restrict__ x, int xcs, int xbs,
    const float* __restrict__ w,   // [256][256][3]
    const float* __restrict__ bias,
    float* __restrict__ y, int ycs, int ybs, int L)
{
    __shared__ float xs[16][136];       // 16 ci x (128+2) positions
    __shared__ float ws[16][128];       // [ci][co] for current kw slice

    const int tid = threadIdx.x;
    const int lg = tid & 15;            // 16 l-groups of 8
    const int cg = tid >> 4;            // 32 co-groups of 4
    const int lb = lg * 8;
    const int cb = cg * 4;
    const int lBase = blockIdx.x * 128;
    const int coBase = blockIdx.y * 128;
    const int b = blockIdx.z;
    const float* xb = x + (long long)b * xbs;

    float carry[4][8];
    float part[4][8];
#pragma unroll
    for (int o = 0; o < 4; o++)
#pragma unroll
        for (int q = 0; q < 8; q++) carry[o][q] = 0.f;

    const int co_ld = tid & 127;        // weight-load lane: one co
    const int ci_ld = (tid >> 7) * 4;   // 4 ci per thread

    for (int kw = 0; kw < 3; kw++) {
#pragma unroll
        for (int o = 0; o < 4; o++)
#pragma unroll
            for (int q = 0; q < 8; q++) part[o][q] = 0.f;

        for (int c0 = 0; c0 < 256; c0 += 16) {
            // x tile: 16 ci x 130 positions (l-1 .. l+128)
            for (int idx = tid; idx < 16 * 130; idx += 512) {
                int ci = idx / 130;
                int ll = idx - ci * 130;
                int gl = lBase + ll - 1;
                float v = 0.f;
                if (gl >= 0 && gl < L) v = xb[(c0 + ci) * xcs + gl];
                xs[ci][ll] = v;
            }
            // w slice for this kw: ws[ci][co]
            {
                const float* wp = w + (coBase + co_ld) * 768;
#pragma unroll
                for (int j = 0; j < 4; j++) {
                    int ci = ci_ld + j;
                    ws[ci][co_ld] = wp[(c0 + ci) * 3 + kw];
                }
            }
            __syncthreads();

#pragma unroll
            for (int ci = 0; ci < 16; ci++) {
                float wv[4];
#pragma unroll
                for (int o = 0; o < 4; o++) wv[o] = ws[ci][cb + o];
                float xv[8];
#pragma unroll
                for (int q = 0; q < 8; q++) xv[q] = xs[ci][lb + kw + q];
#pragma unroll
                for (int o = 0; o < 4; o++)
#pragma unroll
                    for (int q = 0; q < 8; q++)
                        part[o][q] = fmaf(wv[o], xv[q], part[o][q]);
            }
            __syncthreads();
        }

        // combine k-block into C (Eigen C-update: one fp32 add per block)
#pragma unroll
        for (int o = 0; o < 4; o++)
#pragma unroll
            for (int q = 0; q < 8; q++)
                carry[o][q] = __fadd_rn(carry[o][q], part[o][q]);
    }

    float* yb = y + (long long)b * ybs;
#pragma unroll
    for (int o = 0; o < 4; o++) {
        float bv = bias[coBase + cb + o];
#pragma unroll
        for (int q = 0; q < 8; q++) {
            float v = __fadd_rn(carry[o][q], bv);
            if (RELU) v = fmaxf(v, 0.f);
            yb[(coBase + cb + o) * ycs + lBase + lb + q] = v;
        }
    }
}

// ---------------- small-Cout prediction conv (no relu), same blocking ----
__global__ void __launch_bounds__(320) convpred_kernel(
    const float* __restrict__ x, int xcs, int xbs,
    const float* __restrict__ w,   // [Cout][256][3]
    const float* __restrict__ bias,
    float* __restrict__ y, int ycs, int ybs, int L, int Cout)
{
    __shared__ float xs[32][72];
    __shared__ float ws[32][40];

    const int tid = threadIdx.x;
    const int co = tid >> 3;
    const int lg = tid & 7;
    const int lBase = blockIdx.x * 64;
    const int b = blockIdx.y;
    const float* xb = x + (long long)b * xbs;

    float carry[8], part[8];
#pragma unroll
    for (int q = 0; q < 8; q++) carry[q] = 0.f;

    const int wcount = Cout * 32;
    for (int kw = 0; kw < 3; kw++) {
#pragma unroll
        for (int q = 0; q < 8; q++) part[q] = 0.f;

        for (int c0 = 0; c0 < 256; c0 += 32) {
            for (int idx = tid; idx < 32 * 66; idx += 320) {
                int ci = idx / 66;
                int ll = idx - ci * 66;
                int gl = lBase + ll - 1;
                xs[ci][ll] = (gl >= 0 && gl < L) ? xb[(c0 + ci) * xcs + gl] : 0.f;
            }
            for (int idx = tid; idx < wcount; idx += 320) {
                int c = idx >> 5;
                int r = idx & 31;
                ws[r][c] = w[c * 768 + (c0 + r) * 3 + kw];
            }
            __syncthreads();

            if (co < Cout) {
#pragma unroll
                for (int ci = 0; ci < 32; ci++) {
                    float wv = ws[ci][co];
#pragma unroll
                    for (int q = 0; q < 8; q++)
                        part[q] = fmaf(wv, xs[ci][lg * 8 + kw + q], part[q]);
                }
            }
            __syncthreads();
        }

#pragma unroll
        for (int q = 0; q < 8; q++) carry[q] = __fadd_rn(carry[q], part[q]);
    }

    if (co < Cout) {
        float bv = bias[co];
        float* yb = y + (long long)b * ybs;
#pragma unroll
        for (int q = 0; q < 8; q++)
            yb[co * ycs + lBase + lg * 8 + q] = __fadd_rn(carry[q], bv);
    }
}

// ---------------- per-anchor sort key (logit bits) + decoded segment ----
__global__ void score_kernel()
{
    int id = blockIdx.x * 256 + threadIdx.x;
    int b = id >> 13;
    int a = id & (NSORT - 1);
    if (a >= ATOT) { g_keys[id] = 0ULL; return; }

    int lvl, al;
    if (a < 4096)      { lvl = 0; al = a; }
    else if (a < 6144) { lvl = 1; al = a - 4096; }
    else               { lvl = 2; al = a - 6144; }

    const int   Ls[3]     = {2048, 1024, 512};
    const int   off[3]    = {0, 2048, 3072};
    const int   strides[3]= {8, 16, 32};
    const float lens[3][2]= {{16.f, 32.f}, {64.f, 128.f}, {256.f, 512.f}};

    int L = Ls[lvl];
    int ap = al / L;
    int l  = al - ap * L;

    const float* lp = g_logits + ((long long)(b * APER + ap) * NCLS) * LTOT + off[lvl] + l;
    float m = -1e30f;
#pragma unroll
    for (int c = 0; c < NCLS; c++) m = fmaxf(m, lp[c * LTOT]);

    unsigned mb = __float_as_uint(m);
    mb ^= (mb & 0x80000000u) ? 0xFFFFFFFFu : 0x80000000u;
    unsigned long long key =
        ((unsigned long long)mb << 32) |
        (unsigned long long)(0xFFFFFFFFu - (unsigned)a);
    g_keys[id] = key;

    float r0 = g_regs[((long long)(b * APER + ap) * 2 + 0) * LTOT + off[lvl] + l];
    float r1 = g_regs[((long long)(b * APER + ap) * 2 + 1) * LTOT + off[lvl] + l];
    float c_ = (l + 0.5f) * (float)strides[lvl];
    float h  = lens[lvl][ap] * 0.5f;
    float s0 = rintf(c_ - h);
    float s1 = rintf(c_ + h);
    g_segs[((long long)b * ATOT + a) * 2 + 0] = __fadd_rn(s0, r0);
    g_segs[((long long)b * ATOT + a) * 2 + 1] = __fadd_rn(s1, r1);
}

// ---------------- per-batch bitonic sort (descending) ----------------
__global__ void sort_kernel()
{
    extern __shared__ unsigned long long s[];
    const int b = blockIdx.x;
    const int tid = threadIdx.x;

    for (int i = tid; i < NSORT; i += 1024) s[i] = g_keys[b * NSORT + i];
    __syncthreads();

    for (int k = 2; k <= NSORT; k <<= 1) {
        for (int j = k >> 1; j > 0; j >>= 1) {
            for (int i = tid; i < NSORT; i += 1024) {
                int ixj = i ^ j;
                if (ixj > i) {
                    unsigned long long va = s[i], vb = s[ixj];
                    bool desc = ((i & k) == 0);
                    if (desc ? (va < vb) : (va > vb)) { s[i] = vb; s[ixj] = va; }
                }
            }
            __syncthreads();
        }
    }
    for (int i = tid; i < KTOP; i += 1024) g_topkeys[b * KTOP + i] = s[i];
}

// ---------------- per-batch greedy NMS + output ----------------
__global__ void nms_kernel(float* __restrict__ out)
{
    __shared__ float s0[KTOP];
    __shared__ float s1[KTOP];
    __shared__ unsigned char sup[KTOP];

    const int b = blockIdx.x;
    const int tid = threadIdx.x;

    float myscore = 0.f, m0 = 0.f, m1 = 0.f;
    if (tid < KTOP) {
        unsigned long long key = g_topkeys[b * KTOP + tid];
        int a = (int)(0xFFFFFFFFu - (unsigned)(key & 0xFFFFFFFFull));
        unsigned mb = (unsigned)(key >> 32);
        mb ^= (mb & 0x80000000u) ? 0x80000000u : 0xFFFFFFFFu;
        float logit = __uint_as_float(mb);
        myscore = 1.f / (1.f + expf(-logit));
        m0 = g_segs[((long long)b * ATOT + a) * 2 + 0];
        m1 = g_segs[((long long)b * ATOT + a) * 2 + 1];
        s0[tid] = m0; s1[tid] = m1; sup[tid] = 0;
    }
    __syncthreads();

    const float mylen = __fadd_rn(m1, -m0);
    for (int i = 0; i < KTOP - 1; i++) {
        bool act = (sup[i] == 0);
        if (act && tid > i && tid < KTOP && sup[tid] == 0) {
            float a0 = s0[i], a1 = s1[i];
            float inter = fmaxf(__fadd_rn(fminf(a1, m1), -fmaxf(a0, m0)), 0.f);
            float uni = __fadd_rn(__fadd_rn(__fadd_rn(a1, -a0), mylen), -inter);
            float iou = __fdiv_rn(inter, fmaxf(uni, 1e-6f));
            if (iou > 0.5f) sup[tid] = 1;
        }
        __syncthreads();
    }

    if (tid < KTOP) {
        out[((long long)b * KTOP + tid) * 3 + 0] = sup[tid] ? 0.f : myscore;
        out[((long long)b * KTOP + tid) * 3 + 1] = m0;
        out[((long long)b * KTOP + tid) * 3 + 2] = m1;
    }
}

// ---------------- launch ----------------
extern "C" void kernel_launch(void* const* d_in, const int* in_sizes, int n_in,
                              void* d_out, int out_size)
{
    const float* feats[3] = {(const float*)d_in[0], (const float*)d_in[1], (const float*)d_in[2]};
    const float* cls_w  = (const float*)d_in[3];
    const float* cls_b  = (const float*)d_in[4];
    const float* reg_w  = (const float*)d_in[5];
    const float* reg_b  = (const float*)d_in[6];
    const float* clsp_w = (const float*)d_in[7];
    const float* clsp_b = (const float*)d_in[8];
    const float* regp_w = (const float*)d_in[9];
    const float* regp_b = (const float*)d_in[10];
    float* out = (float*)d_out;

    const int Ls[3]  = {2048, 1024, 512};
    const int off[3] = {0, 2048, 3072};

    void* pA; cudaGetSymbolAddress(&pA, g_bufA);
    void* pB; cudaGetSymbolAddress(&pB, g_bufB);
    void* pL; cudaGetSymbolAddress(&pL, g_logits);
    void* pR; cudaGetSymbolAddress(&pR, g_regs);
    float* A = (float*)pA;
    float* Bf = (float*)pB;
    float* logits = (float*)pL;
    float* regs = (float*)pR;

    for (int tower = 0; tower < 2; tower++) {
        const float* tw = tower ? reg_w : cls_w;
        const float* tb = tower ? reg_b : cls_b;
        for (int lvl = 0; lvl < 3; lvl++) {
            int L = Ls[lvl];
            dim3 grid(L / 128, 2, BB);
            conv256_kernel<true><<<grid, 512>>>(feats[lvl], L, CC * L,
                                                tw, tb,
                                                A + off[lvl], LTOT, CC * LTOT, L);
            float* cur = A + off[lvl];
            float* nxt = Bf + off[lvl];
            for (int i = 1; i < 4; i++) {
                conv256_kernel<true><<<grid, 512>>>(cur, LTOT, CC * LTOT,
                                                    tw + i * (256 * 256 * 3), tb + i * 256,
                                                    nxt, LTOT, CC * LTOT, L);
                float* t = cur; cur = nxt; nxt = t;
            }
            dim3 pgrid(L / 64, BB);
            if (tower == 0)
                convpred_kernel<<<pgrid, 320>>>(cur, LTOT, CC * LTOT,
                                                clsp_w, clsp_b,
                                                logits + off[lvl], LTOT, APER * NCLS * LTOT, L,
                                                APER * NCLS);
            else
                convpred_kernel<<<pgrid, 320>>>(cur, LTOT, CC * LTOT,
                                                regp_w, regp_b,
                                                regs + off[lvl], LTOT, APER * 2 * LTOT, L,
                                                APER * 2);
        }
    }

    score_kernel<<<(BB * NSORT) / 256, 256>>>();

    cudaFuncSetAttribute(sort_kernel, cudaFuncAttributeMaxDynamicSharedMemorySize,
                         NSORT * (int)sizeof(unsigned long long));
    sort_kernel<<<BB, 1024, NSORT * sizeof(unsigned long long)>>>();

    nms_kernel<<<BB, 1024>>>(out);
}

// round 8
// speedup vs baseline: 3.5670x; 3.5670x over previous
#include <cuda_runtime.h>
#include <math.h>

#define BB    8
#define CC    256
#define NCLS  20
#define APER  2
#define LTOT  3584
#define ATOT  7168
#define KTOP  1000
#define NSORT 8192

// ---------------- scratch (device globals; no allocation) ----------------
__device__ float g_bufA[BB * CC * LTOT];   // cls ping
__device__ float g_bufB[BB * CC * LTOT];   // cls pong
__device__ float g_bufC[BB * CC * LTOT];   // reg ping
__device__ float g_bufD[BB * CC * LTOT];   // reg pong
__device__ float g_Gc[3 * BB * CC * LTOT]; // per-kw partial sums, cls tower
__device__ float g_Gr[3 * BB * CC * LTOT]; // per-kw partial sums, reg tower
__device__ float g_wt_c[3 * CC * CC];      // transposed weights [kw][ci][co]
__device__ float g_wt_r[3 * CC * CC];
__device__ float g_logits[BB * APER * NCLS * LTOT];
__device__ float g_regs[BB * APER * 2 * LTOT];
__device__ float g_segs[BB * ATOT * 2];
__device__ unsigned long long g_keys[BB * NSORT];
__device__ unsigned long long g_topkeys[BB * KTOP];

// ---------------- weight transpose: w[co][ci][3] -> wt[kw][ci][co] -------
__global__ void wtrans_kernel(const float* __restrict__ wc,
                              const float* __restrict__ wr)
{
    int idx = blockIdx.x * 256 + threadIdx.x;      // 0 .. 2*3*256*256-1
    int tower = idx / 196608;
    int r = idx - tower * 196608;
    int kw = r / 65536;
    int rem = r - kw * 65536;
    int ci = rem >> 8;
    int co = rem & 255;
    const float* w = tower ? wr : wc;
    float v = w[co * 768 + ci * 3 + kw];
    (tower ? g_wt_r : g_wt_c)[r] = v;
}

// ---------------- per-kw GEMM: G_kw[co][l] = sum_ci wt[kw][ci][co]*x[ci][l]
// Single sequential fma chain over ci=0..255 (one Eigen k-block). 128co x
// 128l tile, 256 threads, 8x8 register tile. Grid: x = b*28 + levelblock,
// y = co-half, z = tower*3 + kw.
__global__ void __launch_bounds__(256, 2) gemm_kernel(
    const float* __restrict__ f3, const float* __restrict__ f4,
    const float* __restrict__ f5,
    const float* __restrict__ xc, const float* __restrict__ xr,
    int layer0)
{
    __shared__ float xs[16][128];
    __shared__ float ws[16][128];

    const int tid = threadIdx.x;
    const int lbb = blockIdx.x;
    const int b = lbb / 28;
    const int lb = lbb - b * 28;
    const int lvl = (lb < 16) ? 0 : ((lb < 24) ? 1 : 2);
    const int Ls[3]  = {2048, 1024, 512};
    const int off[3] = {0, 2048, 3072};
    const int st[3]  = {0, 16, 24};
    const int lBase = (lb - st[lvl]) * 128;
    const int coBase = blockIdx.y * 128;
    const int z = blockIdx.z;
    const int tower = z / 3;
    const int kw = z - tower * 3;

    const float* x;
    int xcs_;
    long long xofs;
    if (layer0) {
        x = (lvl == 0) ? f3 : ((lvl == 1) ? f4 : f5);
        xcs_ = Ls[lvl];
        xofs = (long long)b * (256 * Ls[lvl]);
    } else {
        x = tower ? xr : xc;
        xcs_ = LTOT;
        xofs = (long long)b * (256 * LTOT) + off[lvl];
    }
    const float* wt = (tower ? g_wt_r : g_wt_c) + kw * 65536 + coBase;
    float* G = tower ? g_Gr : g_Gc;

    float acc[8][8];
#pragma unroll
    for (int o = 0; o < 8; o++)
#pragma unroll
        for (int q = 0; q < 8; q++) acc[o][q] = 0.f;

    const int lg = tid & 15;
    const int cg = tid >> 4;
    const int lb8 = lg * 8;
    const int cb = cg * 8;

    const int ldrow = tid >> 4;        // 0..15 (ci within chunk)
    const int ldcol = (tid & 15) * 8;  // 0..120

    for (int c0 = 0; c0 < 256; c0 += 16) {
        {
            const float* xp = x + xofs + (long long)(c0 + ldrow) * xcs_ + lBase + ldcol;
            float4 v0 = *(const float4*)xp;
            float4 v1 = *(const float4*)(xp + 4);
            *(float4*)&xs[ldrow][ldcol] = v0;
            *(float4*)&xs[ldrow][ldcol + 4] = v1;
        }
        {
            const float* wp = wt + (c0 + ldrow) * 256 + ldcol;
            float4 v0 = *(const float4*)wp;
            float4 v1 = *(const float4*)(wp + 4);
            *(float4*)&ws[ldrow][ldcol] = v0;
            *(float4*)&ws[ldrow][ldcol + 4] = v1;
        }
        __syncthreads();

#pragma unroll
        for (int ci = 0; ci < 16; ci++) {
            float4 xa = *(const float4*)&xs[ci][lb8];
            float4 xb = *(const float4*)&xs[ci][lb8 + 4];
            float4 wa = *(const float4*)&ws[ci][cb];
            float4 wb = *(const float4*)&ws[ci][cb + 4];
            float xv[8] = {xa.x, xa.y, xa.z, xa.w, xb.x, xb.y, xb.z, xb.w};
            float wv[8] = {wa.x, wa.y, wa.z, wa.w, wb.x, wb.y, wb.z, wb.w};
#pragma unroll
            for (int o = 0; o < 8; o++)
#pragma unroll
                for (int q = 0; q < 8; q++)
                    acc[o][q] = fmaf(wv[o], xv[q], acc[o][q]);
        }
        __syncthreads();
    }

#pragma unroll
    for (int o = 0; o < 8; o++) {
        float* gp = G + ((long long)((kw * BB + b) * CC + coBase + cb + o)) * LTOT
                      + off[lvl] + lBase + lb8;
        float4 v0 = {acc[o][0], acc[o][1], acc[o][2], acc[o][3]};
        float4 v1 = {acc[o][4], acc[o][5], acc[o][6], acc[o][7]};
        *(float4*)gp = v0;
        *(float4*)(gp + 4) = v1;
    }
}

// ---------------- combine: y = relu(((G0[l-1]+G1[l])+G2[l+1]) + bias) ----
__global__ void combine_kernel(float* __restrict__ outc, float* __restrict__ outr,
                               const float* __restrict__ bc, const float* __restrict__ br)
{
    const int off[3] = {0, 2048, 3072};
    const int Ls[3]  = {2048, 1024, 512};

    long long idx = ((long long)blockIdx.x * 256 + threadIdx.x) * 4;
    // layout: tower, b, co, l(LTOT)
    int l = (int)(idx % LTOT);
    long long row = idx / LTOT;
    int co = (int)(row & 255);
    long long r2 = row >> 8;
    int b = (int)(r2 & 7);
    int tower = (int)(r2 >> 3);

    int lvl = (l < 2048) ? 0 : ((l < 3072) ? 1 : 2);
    int loc = l - off[lvl];
    int L = Ls[lvl];

    const float* G = tower ? g_Gr : g_Gc;
    long long base = ((long long)b * CC + co) * LTOT;
    const float* G0 = G + base;                               // kw=0
    const float* G1 = G + (long long)BB * CC * LTOT + base;   // kw=1
    const float* G2 = G + 2LL * BB * CC * LTOT + base;        // kw=2
    float bias = (tower ? br : bc)[co];
    float* out = (tower ? outr : outc) + base;

#pragma unroll
    for (int j = 0; j < 4; j++) {
        int ll = loc + j;
        float s0 = (ll > 0)     ? G0[l + j - 1] : 0.f;
        float s1 = G1[l + j];
        float s2 = (ll + 1 < L) ? G2[l + j + 1] : 0.f;
        float v = __fadd_rn(__fadd_rn(__fadd_rn(s0, s1), s2), bias);
        out[l + j] = fmaxf(v, 0.f);
    }
}

// ---------------- small-Cout prediction conv (R7, bit-exact) -------------
__global__ void __launch_bounds__(320) convpred_kernel(
    const float* __restrict__ x, int xcs, int xbs,
    const float* __restrict__ w,   // [Cout][256][3]
    const float* __restrict__ bias,
    float* __restrict__ y, int ycs, int ybs, int L, int Cout)
{
    __shared__ float xs[32][72];
    __shared__ float ws[32][40];

    const int tid = threadIdx.x;
    const int co = tid >> 3;
    const int lg = tid & 7;
    const int lBase = blockIdx.x * 64;
    const int b = blockIdx.y;
    const float* xb = x + (long long)b * xbs;

    float carry[8], part[8];
#pragma unroll
    for (int q = 0; q < 8; q++) carry[q] = 0.f;

    const int wcount = Cout * 32;
    for (int kw = 0; kw < 3; kw++) {
#pragma unroll
        for (int q = 0; q < 8; q++) part[q] = 0.f;

        for (int c0 = 0; c0 < 256; c0 += 32) {
            for (int idx = tid; idx < 32 * 66; idx += 320) {
                int ci = idx / 66;
                int ll = idx - ci * 66;
                int gl = lBase + ll - 1;
                xs[ci][ll] = (gl >= 0 && gl < L) ? xb[(c0 + ci) * xcs + gl] : 0.f;
            }
            for (int idx = tid; idx < wcount; idx += 320) {
                int c = idx >> 5;
                int r = idx & 31;
                ws[r][c] = w[c * 768 + (c0 + r) * 3 + kw];
            }
            __syncthreads();

            if (co < Cout) {
#pragma unroll
                for (int ci = 0; ci < 32; ci++) {
                    float wv = ws[ci][co];
#pragma unroll
                    for (int q = 0; q < 8; q++)
                        part[q] = fmaf(wv, xs[ci][lg * 8 + kw + q], part[q]);
                }
            }
            __syncthreads();
        }

#pragma unroll
        for (int q = 0; q < 8; q++) carry[q] = __fadd_rn(carry[q], part[q]);
    }

    if (co < Cout) {
        float bv = bias[co];
        float* yb = y + (long long)b * ybs;
#pragma unroll
        for (int q = 0; q < 8; q++)
            yb[co * ycs + lBase + lg * 8 + q] = __fadd_rn(carry[q], bv);
    }
}

// ---------------- per-anchor sort key (logit bits) + decoded segment ----
__global__ void score_kernel()
{
    int id = blockIdx.x * 256 + threadIdx.x;
    int b = id >> 13;
    int a = id & (NSORT - 1);
    if (a >= ATOT) { g_keys[id] = 0ULL; return; }

    int lvl, al;
    if (a < 4096)      { lvl = 0; al = a; }
    else if (a < 6144) { lvl = 1; al = a - 4096; }
    else               { lvl = 2; al = a - 6144; }

    const int   Ls[3]     = {2048, 1024, 512};
    const int   off[3]    = {0, 2048, 3072};
    const int   strides[3]= {8, 16, 32};
    const float lens[3][2]= {{16.f, 32.f}, {64.f, 128.f}, {256.f, 512.f}};

    int L = Ls[lvl];
    int ap = al / L;
    int l  = al - ap * L;

    const float* lp = g_logits + ((long long)(b * APER + ap) * NCLS) * LTOT + off[lvl] + l;
    float m = -1e30f;
#pragma unroll
    for (int c = 0; c < NCLS; c++) m = fmaxf(m, lp[c * LTOT]);

    unsigned mb = __float_as_uint(m);
    mb ^= (mb & 0x80000000u) ? 0xFFFFFFFFu : 0x80000000u;
    unsigned long long key =
        ((unsigned long long)mb << 32) |
        (unsigned long long)(0xFFFFFFFFu - (unsigned)a);
    g_keys[id] = key;

    float r0 = g_regs[((long long)(b * APER + ap) * 2 + 0) * LTOT + off[lvl] + l];
    float r1 = g_regs[((long long)(b * APER + ap) * 2 + 1) * LTOT + off[lvl] + l];
    float c_ = (l + 0.5f) * (float)strides[lvl];
    float h  = lens[lvl][ap] * 0.5f;
    float s0 = rintf(c_ - h);
    float s1 = rintf(c_ + h);
    g_segs[((long long)b * ATOT + a) * 2 + 0] = __fadd_rn(s0, r0);
    g_segs[((long long)b * ATOT + a) * 2 + 1] = __fadd_rn(s1, r1);
}

// ---------------- per-batch bitonic sort (descending) ----------------
__global__ void sort_kernel()
{
    extern __shared__ unsigned long long s[];
    const int b = blockIdx.x;
    const int tid = threadIdx.x;

    for (int i = tid; i < NSORT; i += 1024) s[i] = g_keys[b * NSORT + i];
    __syncthreads();

    for (int k = 2; k <= NSORT; k <<= 1) {
        for (int j = k >> 1; j > 0; j >>= 1) {
            for (int i = tid; i < NSORT; i += 1024) {
                int ixj = i ^ j;
                if (ixj > i) {
                    unsigned long long va = s[i], vb = s[ixj];
                    bool desc = ((i & k) == 0);
                    if (desc ? (va < vb) : (va > vb)) { s[i] = vb; s[ixj] = va; }
                }
            }
            __syncthreads();
        }
    }
    for (int i = tid; i < KTOP; i += 1024) g_topkeys[b * KTOP + i] = s[i];
}

// ---------------- per-batch greedy NMS + output ----------------
__global__ void nms_kernel(float* __restrict__ out)
{
    __shared__ float s0[KTOP];
    __shared__ float s1[KTOP];
    __shared__ unsigned char sup[KTOP];

    const int b = blockIdx.x;
    const int tid = threadIdx.x;

    float myscore = 0.f, m0 = 0.f, m1 = 0.f;
    if (tid < KTOP) {
        unsigned long long key = g_topkeys[b * KTOP + tid];
        int a = (int)(0xFFFFFFFFu - (unsigned)(key & 0xFFFFFFFFull));
        unsigned mb = (unsigned)(key >> 32);
        mb ^= (mb & 0x80000000u) ? 0x80000000u : 0xFFFFFFFFu;
        float logit = __uint_as_float(mb);
        myscore = 1.f / (1.f + expf(-logit));
        m0 = g_segs[((long long)b * ATOT + a) * 2 + 0];
        m1 = g_segs[((long long)b * ATOT + a) * 2 + 1];
        s0[tid] = m0; s1[tid] = m1; sup[tid] = 0;
    }
    __syncthreads();

    const float mylen = __fadd_rn(m1, -m0);
    for (int i = 0; i < KTOP - 1; i++) {
        bool act = (sup[i] == 0);
        if (act && tid > i && tid < KTOP && sup[tid] == 0) {
            float a0 = s0[i], a1 = s1[i];
            float inter = fmaxf(__fadd_rn(fminf(a1, m1), -fmaxf(a0, m0)), 0.f);
            float uni = __fadd_rn(__fadd_rn(__fadd_rn(a1, -a0), mylen), -inter);
            float iou = __fdiv_rn(inter, fmaxf(uni, 1e-6f));
            if (iou > 0.5f) sup[tid] = 1;
        }
        __syncthreads();
    }

    if (tid < KTOP) {
        out[((long long)b * KTOP + tid) * 3 + 0] = sup[tid] ? 0.f : myscore;
        out[((long long)b * KTOP + tid) * 3 + 1] = m0;
        out[((long long)b * KTOP + tid) * 3 + 2] = m1;
    }
}

// ---------------- launch ----------------
extern "C" void kernel_launch(void* const* d_in, const int* in_sizes, int n_in,
                              void* d_out, int out_size)
{
    const float* feats[3] = {(const float*)d_in[0], (const float*)d_in[1], (const float*)d_in[2]};
    const float* cls_w  = (const float*)d_in[3];
    const float* cls_b  = (const float*)d_in[4];
    const float* reg_w  = (const float*)d_in[5];
    const float* reg_b  = (const float*)d_in[6];
    const float* clsp_w = (const float*)d_in[7];
    const float* clsp_b = (const float*)d_in[8];
    const float* regp_w = (const float*)d_in[9];
    const float* regp_b = (const float*)d_in[10];
    float* out = (float*)d_out;

    const int Ls[3]  = {2048, 1024, 512};
    const int off[3] = {0, 2048, 3072};

    void* p;
    cudaGetSymbolAddress(&p, g_bufA); float* Ac = (float*)p;
    cudaGetSymbolAddress(&p, g_bufB); float* Bc = (float*)p;
    cudaGetSymbolAddress(&p, g_bufC); float* Ar = (float*)p;
    cudaGetSymbolAddress(&p, g_bufD); float* Br = (float*)p;
    cudaGetSymbolAddress(&p, g_logits); float* logits = (float*)p;
    cudaGetSymbolAddress(&p, g_regs);   float* regs = (float*)p;

    float* in_c = nullptr; float* in_r = nullptr;
    float* out_c = Ac;     float* out_r = Ar;

    for (int layer = 0; layer < 4; layer++) {
        wtrans_kernel<<<1536, 256>>>(cls_w + layer * 196608, reg_w + layer * 196608);
        gemm_kernel<<<dim3(224, 2, 6), 256>>>(feats[0], feats[1], feats[2],
                                              in_c, in_r, layer == 0);
        combine_kernel<<<14336, 256>>>(out_c, out_r,
                                       cls_b + layer * 256, reg_b + layer * 256);
        in_c = out_c; in_r = out_r;
        out_c = (out_c == Ac) ? Bc : Ac;
        out_r = (out_r == Ar) ? Br : Ar;
    }
    // towers end in in_c (cls), in_r (reg)

    for (int lvl = 0; lvl < 3; lvl++) {
        int L = Ls[lvl];
        dim3 pgrid(L / 64, BB);
        convpred_kernel<<<pgrid, 320>>>(in_c + off[lvl], LTOT, CC * LTOT,
                                        clsp_w, clsp_b,
                                        logits + off[lvl], LTOT, APER * NCLS * LTOT, L,
                                        APER * NCLS);
        convpred_kernel<<<pgrid, 320>>>(in_r + off[lvl], LTOT, CC * LTOT,
                                        regp_w, regp_b,
                                        regs + off[lvl], LTOT, APER * 2 * LTOT, L,
                                        APER * 2);
    }

    score_kernel<<<(BB * NSORT) / 256, 256>>>();

    cudaFuncSetAttribute(sort_kernel, cudaFuncAttributeMaxDynamicSharedMemorySize,
                         NSORT * (int)sizeof(unsigned long long));
    sort_kernel<<<BB, 1024, NSORT * sizeof(unsigned long long)>>>();

    nms_kernel<<<BB, 1024>>>(out);
}